// round 5
// baseline (speedup 1.0000x reference)
#include <cuda_runtime.h>
#include <math.h>

#define BB 16
#define TT 96
#define NN 256
#define CC 9
#define MM (NN*CC)          // 2304
#define EE 128
#define HID 64
#define KNN 8
#define PRED 96
#define BM (BB*MM)          // 36864
#define BN (BB*NN)          // 4096

// ---------------- device scratch (static, no allocation) ----------------
__device__ float d_trend[BN*TT];          // (b,n,t)
__device__ float d_sgr[BM], d_sgi[BM];    // spectral node scalars
__device__ int   d_idx[BM*KNN];
__device__ float d_indeg[BM];
__device__ float d_dinv[BM];
__device__ float d_gr[BM*CC], d_gi[BM*CC];
__device__ float d_g2r[BM*CC], d_g2i[BM*CC];
__device__ float d_soutr[BM], d_souti[BM];
__device__ float d_H[BN*TT];
__device__ float d_H1[BN*HID];
__device__ float d_G[BN*HID];
__device__ float d_Ar[CC*EE], d_Ai[CC*EE];
__device__ float d_tw16c[16], d_tw16s[16];
__device__ float d_tw96c[96], d_tw96s[96];

// ---------------- zero scratch ----------------
__global__ void k_zero() {
    int i = blockIdx.x * blockDim.x + threadIdx.x;
    if (i < BM*CC) {
        d_gr[i] = 0.f; d_gi[i] = 0.f; d_g2r[i] = 0.f; d_g2i[i] = 0.f;
    }
    if (i < BM) d_indeg[i] = 0.f;
}

// ---------------- precompute: twiddles + projected weight matrices ----------------
__global__ void k_pre(const float* __restrict__ femb,
                      const float* __restrict__ frWr,
                      const float* __restrict__ frWi) {
    if (blockIdx.x < CC) {
        int c = blockIdx.x, e = threadIdx.x;     // 128 threads
        float sr = 0.f, si = 0.f;
        const float* fe = femb + c*EE;
        const float* wr = frWr + e*EE;
        const float* wi = frWi + e*EE;
        #pragma unroll 8
        for (int k = 0; k < EE; ++k) {
            float f = fe[k];
            sr += f * wr[k];
            si += f * wi[k];
        }
        d_Ar[c*EE + e] = sr;
        d_Ai[c*EE + e] = si;
    } else {
        int t = threadIdx.x;
        if (t < 96) {
            double a = 2.0 * 3.14159265358979323846 * (double)t / 96.0;
            d_tw96c[t] = (float)cos(a);
            d_tw96s[t] = (float)sin(a);
        }
        if (t < 16) {
            double a = 2.0 * 3.14159265358979323846 * (double)t / 16.0;
            d_tw16c[t] = (float)cos(a);
            d_tw16s[t] = (float)sin(a);
        }
    }
}

// ---------------- trend (moving avg) + truncated 16-pt rDFT ----------------
__global__ void k_trend_dft(const float* __restrict__ x) {
    int id = blockIdx.x * blockDim.x + threadIdx.x;
    if (id >= BN) return;
    int b = id >> 8, n = id & 255;
    const float* xb = x + (size_t)b*TT*NN + n;
    float s[16];
    float xprev = xb[0];
    float xc = xb[0];
    for (int t = 0; t < TT; ++t) {
        float xn = (t < TT-1) ? xb[(t+1)*NN] : xc;
        float tr = (xprev + xc + xn) / 3.0f;
        d_trend[(size_t)id*TT + t] = tr;
        if (t < 16) s[t] = xc - tr;
        xprev = xc; xc = xn;
    }
    int base = b*MM + n*CC;
    #pragma unroll
    for (int c = 0; c < CC; ++c) {
        float sr = 0.f, si = 0.f;
        #pragma unroll
        for (int t = 0; t < 16; ++t) {
            int a = (c*t) & 15;
            sr += s[t] * d_tw16c[a];
            si -= s[t] * d_tw16s[a];
        }
        d_sgr[base + c] = 0.25f * sr;
        d_sgi[base + c] = 0.25f * si;
    }
}

// ---------------- per-batch KNN: 8 threads/node, stable top-8 merge ----------------
// block = 256 threads = 32 nodes x 8 slices; grid = (72, 16)
__global__ void __launch_bounds__(256) k_knn() {
    __shared__ float sfr[MM], sfi[MM], ssq[MM];
    __shared__ float smd[32][64];
    __shared__ int   smi[32][64];
    int b = blockIdx.y;
    for (int m = threadIdx.x; m < MM; m += 256) {
        float fr = d_sgr[b*MM + m], fi = d_sgi[b*MM + m];
        sfr[m] = fr; sfi[m] = fi; ssq[m] = fr*fr + fi*fi;
    }
    __syncthreads();
    int nl  = threadIdx.x >> 3;           // node-local 0..31
    int sub = threadIdx.x & 7;            // slice 0..7
    int i = blockIdx.x * 32 + nl;         // node 0..MM-1
    float fr = sfr[i], fi = sfi[i], sq = ssq[i];
    float bd[KNN]; int bix[KNN];
    #pragma unroll
    for (int k = 0; k < KNN; ++k) { bd[k] = __int_as_float(0x7f800000); bix[k] = 0x7fffffff; }
    int j0 = sub * (MM/8), j1 = j0 + (MM/8);
    for (int j = j0; j < j1; ++j) {
        if (j == i) continue;
        float dot = fr*sfr[j] + fi*sfi[j];
        float d2 = (sq + ssq[j]) - 2.0f*dot;
        if (d2 < bd[KNN-1]) {
            int p = KNN-1;
            while (p > 0 && d2 < bd[p-1]) { bd[p] = bd[p-1]; bix[p] = bix[p-1]; --p; }
            bd[p] = d2; bix[p] = j;
        }
    }
    #pragma unroll
    for (int k = 0; k < KNN; ++k) { smd[nl][sub*8 + k] = bd[k]; smi[nl][sub*8 + k] = bix[k]; }
    __syncwarp();
    if (sub == 0) {
        float md[KNN]; int mix[KNN];
        #pragma unroll
        for (int k = 0; k < KNN; ++k) { md[k] = __int_as_float(0x7f800000); mix[k] = 0x7fffffff; }
        // iterate slices in order, ranks in order: preserves smaller-index tie-break
        for (int t = 0; t < 64; ++t) {
            float d2 = smd[nl][t];
            if (d2 < md[KNN-1]) {
                int ix = smi[nl][t];
                int p = KNN-1;
                while (p > 0 && d2 < md[p-1]) { md[p] = md[p-1]; mix[p] = mix[p-1]; --p; }
                md[p] = d2; mix[p] = ix;
            }
        }
        int base = (b*MM + i) * KNN;
        #pragma unroll
        for (int k = 0; k < KNN; ++k) {
            d_idx[base + k] = mix[k];
            atomicAdd(&d_indeg[b*MM + mix[k]], 1.0f);
        }
    }
}

__global__ void k_dinv() {
    int i = blockIdx.x * blockDim.x + threadIdx.x;
    if (i < BM) {
        float deg = d_indeg[i] + 8.0f + 1e-8f;
        d_dinv[i] = 1.0f / sqrtf(deg);
    }
}

// ---------------- first graph aggregation: g[m,c] = sum_nb w * sg (per freq bin) ----------------
__global__ void k_g() {
    int e = blockIdx.x * blockDim.x + threadIdx.x;
    if (e >= BM*KNN) return;
    int mi = e >> 3;                 // global node index (b*MM + i)
    int b = mi / MM;
    int mj = b*MM + d_idx[e];
    float w = d_dinv[mi] * d_dinv[mj] * 0.5f;   // ew / S_SCALE
    int ci = mi % CC, cj = mj % CC;
    atomicAdd(&d_gr[mi*CC + cj], w * d_sgr[mj]);
    atomicAdd(&d_gi[mi*CC + cj], w * d_sgi[mj]);
    atomicAdd(&d_gr[mj*CC + ci], w * d_sgr[mi]);
    atomicAdd(&d_gi[mj*CC + ci], w * d_sgi[mi]);
}

// ---------------- second aggregation: g2 = A(g) ----------------
__global__ void k_g2() {
    int e = blockIdx.x * blockDim.x + threadIdx.x;
    if (e >= BM*KNN) return;
    int mi = e >> 3;
    int b = mi / MM;
    int mj = b*MM + d_idx[e];
    float w = d_dinv[mi] * d_dinv[mj] * 0.5f;
    #pragma unroll
    for (int c = 0; c < CC; ++c) {
        atomicAdd(&d_g2r[mi*CC + c], w * d_gr[mj*CC + c]);
        atomicAdd(&d_g2i[mi*CC + c], w * d_gi[mj*CC + c]);
        atomicAdd(&d_g2r[mj*CC + c], w * d_gr[mi*CC + c]);
        atomicAdd(&d_g2i[mj*CC + c], w * d_gi[mi*CC + c]);
    }
}

__device__ __forceinline__ float siluf(float v) { return v / (1.0f + expf(-v)); }

// ---------------- cheb combine + complex projection + csilu + eo dot (warp/node) ----------------
__global__ void __launch_bounds__(256) k_proj(const float* __restrict__ approx,
                                              const float* __restrict__ theta,
                                              const float* __restrict__ eoWr,
                                              const float* __restrict__ eoWi) {
    int gtid = blockIdx.x * blockDim.x + threadIdx.x;
    int m = gtid >> 5;
    int lane = gtid & 31;
    if (m >= BM) return;
    float t0 = theta[0], t1 = theta[1];
    float C0 = t0*approx[0] + t1*approx[3];
    float C1 = t0*approx[1] + t1*approx[4];
    float C2 = t0*approx[2] + t1*approx[5];
    float qr[CC], qi[CC];
    #pragma unroll
    for (int c = 0; c < CC; ++c) {
        qr[c] = -C1 * d_gr[m*CC + c] + 2.0f*C2 * d_g2r[m*CC + c];
        qi[c] = -C1 * d_gi[m*CC + c] + 2.0f*C2 * d_g2i[m*CC + c];
    }
    int cm = m % CC;
    qr[cm] += (C0 - C2) * d_sgr[m];
    qi[cm] += (C0 - C2) * d_sgi[m];
    float pr = 0.f, pi = 0.f;
    #pragma unroll
    for (int eo = 0; eo < 4; ++eo) {
        int e = lane + eo*32;
        float yr = 0.f, yi = 0.f;
        #pragma unroll
        for (int c = 0; c < CC; ++c) {
            float ar = d_Ar[c*EE + e], ai = d_Ai[c*EE + e];
            yr += qr[c]*ar - qi[c]*ai;
            yi += qr[c]*ai + qi[c]*ar;
        }
        float hr = siluf(yr), hi = siluf(yi);
        float er = eoWr[e], ei = eoWi[e];
        pr += hr*er - hi*ei;
        pi += hr*ei + hi*er;
    }
    #pragma unroll
    for (int o = 16; o > 0; o >>= 1) {
        pr += __shfl_xor_sync(0xffffffffu, pr, o);
        pi += __shfl_xor_sync(0xffffffffu, pi, o);
    }
    if (lane == 0) { d_soutr[m] = pr; d_souti[m] = pi; }
}

// ---------------- irfft(n=96) + instance norm + silu (warp/row) ----------------
__global__ void __launch_bounds__(256) k_irfft(const float* __restrict__ n1w,
                                               const float* __restrict__ n1b) {
    int gtid = blockIdx.x * blockDim.x + threadIdx.x;
    int row = gtid >> 5;
    int lane = gtid & 31;
    if (row >= BN) return;
    int b = row >> 8, n = row & 255;
    int base = b*MM + n*CC;
    float Sr[CC], Si[CC];
    #pragma unroll
    for (int c = 0; c < CC; ++c) { Sr[c] = d_soutr[base+c]; Si[c] = d_souti[base+c]; }
    const float inv = 0.10206207261596576f;   // 1/sqrt(96)
    float xs[3];
    float sum = 0.f;
    #pragma unroll
    for (int r = 0; r < 3; ++r) {
        int t = lane + r*32;
        float v = Sr[0];
        #pragma unroll
        for (int k = 1; k < CC; ++k) {
            int a = (k*t) % 96;
            v += 2.0f * (Sr[k]*d_tw96c[a] - Si[k]*d_tw96s[a]);
        }
        xs[r] = v * inv;
        sum += xs[r];
    }
    #pragma unroll
    for (int o = 16; o > 0; o >>= 1) sum += __shfl_xor_sync(0xffffffffu, sum, o);
    float mu = sum / 96.0f;
    float ss = 0.f;
    #pragma unroll
    for (int r = 0; r < 3; ++r) { float d = xs[r]-mu; ss += d*d; }
    #pragma unroll
    for (int o = 16; o > 0; o >>= 1) ss += __shfl_xor_sync(0xffffffffu, ss, o);
    float rstd = 1.0f / sqrtf(ss/96.0f + 1e-5f);
    float w = n1w[n], bia = n1b[n];
    #pragma unroll
    for (int r = 0; r < 3; ++r) {
        int t = lane + r*32;
        float h = (xs[r]-mu)*rstd*w + bia;
        d_H[(size_t)row*TT + t] = siluf(h);
    }
}

// ---------------- H1 = H @ W1^T + b1 ----------------
__global__ void k_H1(const float* __restrict__ W1w, const float* __restrict__ W1b) {
    int id = blockIdx.x * blockDim.x + threadIdx.x;
    if (id >= BN*HID) return;
    int row = id >> 6, h = id & 63;
    const float* hr = d_H + (size_t)row*TT;
    const float* wr = W1w + h*TT;
    float a = W1b[h];
    #pragma unroll 8
    for (int t = 0; t < TT; ++t) a += hr[t] * wr[t];
    d_H1[id] = a;
}

// ---------------- inorm over HID + silu (warp/row, in place) ----------------
__global__ void __launch_bounds__(256) k_inorm2(const float* __restrict__ n2w,
                                                const float* __restrict__ n2b) {
    int gtid = blockIdx.x * blockDim.x + threadIdx.x;
    int row = gtid >> 5;
    int lane = gtid & 31;
    if (row >= BN) return;
    int n = row & 255;
    float v0 = d_H1[row*HID + lane];
    float v1 = d_H1[row*HID + lane + 32];
    float sum = v0 + v1;
    #pragma unroll
    for (int o = 16; o > 0; o >>= 1) sum += __shfl_xor_sync(0xffffffffu, sum, o);
    float mu = sum / 64.0f;
    float d0 = v0-mu, d1 = v1-mu;
    float ss = d0*d0 + d1*d1;
    #pragma unroll
    for (int o = 16; o > 0; o >>= 1) ss += __shfl_xor_sync(0xffffffffu, ss, o);
    float rstd = 1.0f / sqrtf(ss/64.0f + 1e-5f);
    float w = n2w[n], b = n2b[n];
    d_H1[row*HID + lane]      = siluf(d0*rstd*w + b);
    d_H1[row*HID + lane + 32] = siluf(d1*rstd*w + b);
}

// ---------------- G = H1' @ W2^T + b2 + trend @ Wt^T + bt ----------------
__global__ void k_G(const float* __restrict__ W2w, const float* __restrict__ W2b,
                    const float* __restrict__ Wtw, const float* __restrict__ Wtb) {
    int id = blockIdx.x * blockDim.x + threadIdx.x;
    if (id >= BN*HID) return;
    int row = id >> 6, h = id & 63;
    float a = W2b[h] + Wtb[h];
    const float* h1 = d_H1 + row*HID;
    const float* w2 = W2w + h*HID;
    #pragma unroll 8
    for (int k = 0; k < HID; ++k) a += h1[k] * w2[k];
    const float* tr = d_trend + (size_t)row*TT;
    const float* wt = Wtw + h*TT;
    #pragma unroll 8
    for (int t = 0; t < TT; ++t) a += tr[t] * wt[t];
    d_G[id] = a;
}

// ---------------- out = G @ W3^T + b3 ----------------
__global__ void k_out(const float* __restrict__ W3w, const float* __restrict__ W3b,
                      float* __restrict__ out) {
    int id = blockIdx.x * blockDim.x + threadIdx.x;
    if (id >= BN*PRED) return;
    int row = id / PRED, t = id % PRED;
    float a = W3b[t];
    const float* g = d_G + row*HID;
    const float* w = W3w + t*HID;
    #pragma unroll 8
    for (int h = 0; h < HID; ++h) a += g[h] * w[h];
    out[id] = a;
}

// ---------------- launch ----------------
extern "C" void kernel_launch(void* const* d_in, const int* in_sizes, int n_in,
                              void* d_out, int out_size) {
    const float* x     = (const float*)d_in[0];
    const float* approx= (const float*)d_in[1];
    const float* theta = (const float*)d_in[2];
    const float* frWr  = (const float*)d_in[3];
    const float* frWi  = (const float*)d_in[4];
    const float* eoWr  = (const float*)d_in[5];
    const float* eoWi  = (const float*)d_in[6];
    const float* femb  = (const float*)d_in[7];
    const float* n1w   = (const float*)d_in[8];
    const float* n1b   = (const float*)d_in[9];
    const float* n2w   = (const float*)d_in[10];
    const float* n2b   = (const float*)d_in[11];
    const float* W1w   = (const float*)d_in[12];
    const float* W1b   = (const float*)d_in[13];
    const float* W2w   = (const float*)d_in[14];
    const float* W2b   = (const float*)d_in[15];
    const float* Wtw   = (const float*)d_in[16];
    const float* Wtb   = (const float*)d_in[17];
    const float* W3w   = (const float*)d_in[18];
    const float* W3b   = (const float*)d_in[19];
    float* out = (float*)d_out;

    k_zero<<<(BM*CC + 255)/256, 256>>>();
    k_pre<<<CC+1, 128>>>(femb, frWr, frWi);
    k_trend_dft<<<(BN+255)/256, 256>>>(x);
    {
        dim3 grid(MM/32, BB);
        k_knn<<<grid, 256>>>();
    }
    k_dinv<<<(BM+255)/256, 256>>>();
    k_g<<<(BM*KNN + 255)/256, 256>>>();
    k_g2<<<(BM*KNN + 255)/256, 256>>>();
    k_proj<<<(BM*32 + 255)/256, 256>>>(approx, theta, eoWr, eoWi);
    k_irfft<<<(BN*32 + 255)/256, 256>>>(n1w, n1b);
    k_H1<<<(BN*HID + 255)/256, 256>>>(W1w, W1b);
    k_inorm2<<<(BN*32 + 255)/256, 256>>>(n2w, n2b);
    k_G<<<(BN*HID + 255)/256, 256>>>(W2w, W2b, Wtw, Wtb);
    k_out<<<(BN*PRED + 255)/256, 256>>>(W3w, W3b, out);
}

// round 6
// speedup vs baseline: 2.1631x; 2.1631x over previous
#include <cuda_runtime.h>
#include <math.h>

#define BB 16
#define TT 96
#define NN 256
#define CC 9
#define MM (NN*CC)          // 2304
#define EE 128
#define HID 64
#define KNN 8
#define PRED 96
#define BM (BB*MM)          // 36864
#define BN (BB*NN)          // 4096
#define NSL 4               // knn candidate slices
#define SLW (MM/NSL)        // 576 candidates per slice

// ---------------- device scratch (static, no allocation) ----------------
__device__ float d_trend[BN*TT];          // (b,n,t)
__device__ float d_sgr[BM], d_sgi[BM];    // spectral node scalars
__device__ int   d_idx[BM*KNN];
__device__ float d_indeg[BM];
__device__ float d_dinv[BM];
__device__ float d_pd[BM*NSL*KNN];        // partial knn distances
__device__ int   d_pi[BM*NSL*KNN];        // partial knn indices
__device__ float d_gr[BM*CC], d_gi[BM*CC];
__device__ float d_g2r[BM*CC], d_g2i[BM*CC];
__device__ float d_soutr[BM], d_souti[BM];
__device__ float d_H[BN*TT];
__device__ float d_H1[BN*HID];
__device__ float d_G[BN*HID];
__device__ float d_Ar[CC*EE], d_Ai[CC*EE];
__device__ float d_tw16c[16], d_tw16s[16];
__device__ float d_tw96c[96], d_tw96s[96];

// ---------------- zero scratch ----------------
__global__ void k_zero() {
    int i = blockIdx.x * blockDim.x + threadIdx.x;
    if (i < BM*CC) {
        d_gr[i] = 0.f; d_gi[i] = 0.f; d_g2r[i] = 0.f; d_g2i[i] = 0.f;
    }
    if (i < BM) d_indeg[i] = 0.f;
}

// ---------------- precompute: twiddles + projected weight matrices ----------------
__global__ void k_pre(const float* __restrict__ femb,
                      const float* __restrict__ frWr,
                      const float* __restrict__ frWi) {
    if (blockIdx.x < CC) {
        int c = blockIdx.x, e = threadIdx.x;     // 128 threads
        float sr = 0.f, si = 0.f;
        const float* fe = femb + c*EE;
        const float* wr = frWr + e*EE;
        const float* wi = frWi + e*EE;
        #pragma unroll 8
        for (int k = 0; k < EE; ++k) {
            float f = fe[k];
            sr += f * wr[k];
            si += f * wi[k];
        }
        d_Ar[c*EE + e] = sr;
        d_Ai[c*EE + e] = si;
    } else {
        int t = threadIdx.x;
        if (t < 96) {
            double a = 2.0 * 3.14159265358979323846 * (double)t / 96.0;
            d_tw96c[t] = (float)cos(a);
            d_tw96s[t] = (float)sin(a);
        }
        if (t < 16) {
            double a = 2.0 * 3.14159265358979323846 * (double)t / 16.0;
            d_tw16c[t] = (float)cos(a);
            d_tw16s[t] = (float)sin(a);
        }
    }
}

// ---------------- trend (moving avg) + truncated 16-pt rDFT ----------------
__global__ void k_trend_dft(const float* __restrict__ x) {
    int id = blockIdx.x * blockDim.x + threadIdx.x;
    if (id >= BN) return;
    int b = id >> 8, n = id & 255;
    const float* xb = x + (size_t)b*TT*NN + n;
    float s[16];
    float xprev = xb[0];
    float xc = xb[0];
    for (int t = 0; t < TT; ++t) {
        float xn = (t < TT-1) ? xb[(t+1)*NN] : xc;
        float tr = (xprev + xc + xn) / 3.0f;
        d_trend[(size_t)id*TT + t] = tr;
        if (t < 16) s[t] = xc - tr;
        xprev = xc; xc = xn;
    }
    int base = b*MM + n*CC;
    #pragma unroll
    for (int c = 0; c < CC; ++c) {
        float sr = 0.f, si = 0.f;
        #pragma unroll
        for (int t = 0; t < 16; ++t) {
            int a = (c*t) & 15;
            sr += s[t] * d_tw16c[a];
            si -= s[t] * d_tw16s[a];
        }
        d_sgr[base + c] = 0.25f * sr;
        d_sgi[base + c] = 0.25f * si;
    }
}

// ---------------- KNN partial: thread-per-node (broadcast LDS), slice of candidates ----------------
// grid (MM/256, BB, NSL), block 256
__global__ void __launch_bounds__(256) k_knn_part() {
    __shared__ float sfr[MM], sfi[MM], ssq[MM];
    int b = blockIdx.y;
    int z = blockIdx.z;
    for (int m = threadIdx.x; m < MM; m += 256) {
        float fr = d_sgr[b*MM + m], fi = d_sgi[b*MM + m];
        sfr[m] = fr; sfi[m] = fi; ssq[m] = fr*fr + fi*fi;
    }
    __syncthreads();
    int i = blockIdx.x * 256 + threadIdx.x;   // node 0..MM-1
    float fr = sfr[i], fi = sfi[i], sq = ssq[i];
    float bd[KNN]; int bix[KNN];
    #pragma unroll
    for (int k = 0; k < KNN; ++k) { bd[k] = __int_as_float(0x7f800000); bix[k] = 0x7fffffff; }
    int j0 = z * SLW, j1 = j0 + SLW;
    #pragma unroll 2
    for (int j = j0; j < j1; ++j) {
        if (j == i) continue;
        float dot = fr*sfr[j] + fi*sfi[j];
        float d2 = (sq + ssq[j]) - 2.0f*dot;
        if (d2 < bd[KNN-1]) {
            int p = KNN-1;
            while (p > 0 && d2 < bd[p-1]) { bd[p] = bd[p-1]; bix[p] = bix[p-1]; --p; }
            bd[p] = d2; bix[p] = j;
        }
    }
    int base = ((b*MM + i)*NSL + z) * KNN;
    #pragma unroll
    for (int k = 0; k < KNN; ++k) { d_pd[base + k] = bd[k]; d_pi[base + k] = bix[k]; }
}

// ---------------- KNN merge: thread per node, stable (slice, rank) order ----------------
__global__ void k_knn_merge() {
    int m = blockIdx.x * blockDim.x + threadIdx.x;   // global node
    if (m >= BM) return;
    int b = m / MM;
    float md[KNN]; int mix[KNN];
    #pragma unroll
    for (int k = 0; k < KNN; ++k) { md[k] = __int_as_float(0x7f800000); mix[k] = 0x7fffffff; }
    int base = m * NSL * KNN;
    #pragma unroll
    for (int t = 0; t < NSL*KNN; ++t) {
        float d2 = d_pd[base + t];
        if (d2 < md[KNN-1]) {
            int ix = d_pi[base + t];
            int p = KNN-1;
            while (p > 0 && d2 < md[p-1]) { md[p] = md[p-1]; mix[p] = mix[p-1]; --p; }
            md[p] = d2; mix[p] = ix;
        }
    }
    #pragma unroll
    for (int k = 0; k < KNN; ++k) {
        d_idx[m*KNN + k] = mix[k];
        atomicAdd(&d_indeg[b*MM + mix[k]], 1.0f);
    }
}

__global__ void k_dinv() {
    int i = blockIdx.x * blockDim.x + threadIdx.x;
    if (i < BM) {
        float deg = d_indeg[i] + 8.0f + 1e-8f;
        d_dinv[i] = 1.0f / sqrtf(deg);
    }
}

// ---------------- first graph aggregation: g[m,c] = sum_nb w * sg (per freq bin) ----------------
__global__ void k_g() {
    int e = blockIdx.x * blockDim.x + threadIdx.x;
    if (e >= BM*KNN) return;
    int mi = e >> 3;                 // global node index (b*MM + i)
    int b = mi / MM;
    int mj = b*MM + d_idx[e];
    float w = d_dinv[mi] * d_dinv[mj] * 0.5f;   // ew / S_SCALE
    int ci = mi % CC, cj = mj % CC;
    atomicAdd(&d_gr[mi*CC + cj], w * d_sgr[mj]);
    atomicAdd(&d_gi[mi*CC + cj], w * d_sgi[mj]);
    atomicAdd(&d_gr[mj*CC + ci], w * d_sgr[mi]);
    atomicAdd(&d_gi[mj*CC + ci], w * d_sgi[mi]);
}

// ---------------- second aggregation: g2 = A(g) ----------------
__global__ void k_g2() {
    int e = blockIdx.x * blockDim.x + threadIdx.x;
    if (e >= BM*KNN) return;
    int mi = e >> 3;
    int b = mi / MM;
    int mj = b*MM + d_idx[e];
    float w = d_dinv[mi] * d_dinv[mj] * 0.5f;
    #pragma unroll
    for (int c = 0; c < CC; ++c) {
        atomicAdd(&d_g2r[mi*CC + c], w * d_gr[mj*CC + c]);
        atomicAdd(&d_g2i[mi*CC + c], w * d_gi[mj*CC + c]);
        atomicAdd(&d_g2r[mj*CC + c], w * d_gr[mi*CC + c]);
        atomicAdd(&d_g2i[mj*CC + c], w * d_gi[mi*CC + c]);
    }
}

__device__ __forceinline__ float siluf(float v) { return v / (1.0f + expf(-v)); }

// ---------------- cheb combine + complex projection + csilu + eo dot (warp/node) ----------------
__global__ void __launch_bounds__(256) k_proj(const float* __restrict__ approx,
                                              const float* __restrict__ theta,
                                              const float* __restrict__ eoWr,
                                              const float* __restrict__ eoWi) {
    int gtid = blockIdx.x * blockDim.x + threadIdx.x;
    int m = gtid >> 5;
    int lane = gtid & 31;
    if (m >= BM) return;
    float t0 = theta[0], t1 = theta[1];
    float C0 = t0*approx[0] + t1*approx[3];
    float C1 = t0*approx[1] + t1*approx[4];
    float C2 = t0*approx[2] + t1*approx[5];
    float qr[CC], qi[CC];
    #pragma unroll
    for (int c = 0; c < CC; ++c) {
        qr[c] = -C1 * d_gr[m*CC + c] + 2.0f*C2 * d_g2r[m*CC + c];
        qi[c] = -C1 * d_gi[m*CC + c] + 2.0f*C2 * d_g2i[m*CC + c];
    }
    int cm = m % CC;
    qr[cm] += (C0 - C2) * d_sgr[m];
    qi[cm] += (C0 - C2) * d_sgi[m];
    float pr = 0.f, pi = 0.f;
    #pragma unroll
    for (int eo = 0; eo < 4; ++eo) {
        int e = lane + eo*32;
        float yr = 0.f, yi = 0.f;
        #pragma unroll
        for (int c = 0; c < CC; ++c) {
            float ar = d_Ar[c*EE + e], ai = d_Ai[c*EE + e];
            yr += qr[c]*ar - qi[c]*ai;
            yi += qr[c]*ai + qi[c]*ar;
        }
        float hr = siluf(yr), hi = siluf(yi);
        float er = eoWr[e], ei = eoWi[e];
        pr += hr*er - hi*ei;
        pi += hr*ei + hi*er;
    }
    #pragma unroll
    for (int o = 16; o > 0; o >>= 1) {
        pr += __shfl_xor_sync(0xffffffffu, pr, o);
        pi += __shfl_xor_sync(0xffffffffu, pi, o);
    }
    if (lane == 0) { d_soutr[m] = pr; d_souti[m] = pi; }
}

// ---------------- irfft(n=96) + instance norm + silu (warp/row) ----------------
__global__ void __launch_bounds__(256) k_irfft(const float* __restrict__ n1w,
                                               const float* __restrict__ n1b) {
    int gtid = blockIdx.x * blockDim.x + threadIdx.x;
    int row = gtid >> 5;
    int lane = gtid & 31;
    if (row >= BN) return;
    int b = row >> 8, n = row & 255;
    int base = b*MM + n*CC;
    float Sr[CC], Si[CC];
    #pragma unroll
    for (int c = 0; c < CC; ++c) { Sr[c] = d_soutr[base+c]; Si[c] = d_souti[base+c]; }
    const float inv = 0.10206207261596576f;   // 1/sqrt(96)
    float xs[3];
    float sum = 0.f;
    #pragma unroll
    for (int r = 0; r < 3; ++r) {
        int t = lane + r*32;
        float v = Sr[0];
        #pragma unroll
        for (int k = 1; k < CC; ++k) {
            int a = (k*t) % 96;
            v += 2.0f * (Sr[k]*d_tw96c[a] - Si[k]*d_tw96s[a]);
        }
        xs[r] = v * inv;
        sum += xs[r];
    }
    #pragma unroll
    for (int o = 16; o > 0; o >>= 1) sum += __shfl_xor_sync(0xffffffffu, sum, o);
    float mu = sum / 96.0f;
    float ss = 0.f;
    #pragma unroll
    for (int r = 0; r < 3; ++r) { float d = xs[r]-mu; ss += d*d; }
    #pragma unroll
    for (int o = 16; o > 0; o >>= 1) ss += __shfl_xor_sync(0xffffffffu, ss, o);
    float rstd = 1.0f / sqrtf(ss/96.0f + 1e-5f);
    float w = n1w[n], bia = n1b[n];
    #pragma unroll
    for (int r = 0; r < 3; ++r) {
        int t = lane + r*32;
        float h = (xs[r]-mu)*rstd*w + bia;
        d_H[(size_t)row*TT + t] = siluf(h);
    }
}

// ---------------- H1 = H @ W1^T + b1 ----------------
__global__ void k_H1(const float* __restrict__ W1w, const float* __restrict__ W1b) {
    int id = blockIdx.x * blockDim.x + threadIdx.x;
    if (id >= BN*HID) return;
    int row = id >> 6, h = id & 63;
    const float* hr = d_H + (size_t)row*TT;
    const float* wr = W1w + h*TT;
    float a = W1b[h];
    #pragma unroll 8
    for (int t = 0; t < TT; ++t) a += hr[t] * wr[t];
    d_H1[id] = a;
}

// ---------------- inorm over HID + silu (warp/row, in place) ----------------
__global__ void __launch_bounds__(256) k_inorm2(const float* __restrict__ n2w,
                                                const float* __restrict__ n2b) {
    int gtid = blockIdx.x * blockDim.x + threadIdx.x;
    int row = gtid >> 5;
    int lane = gtid & 31;
    if (row >= BN) return;
    int n = row & 255;
    float v0 = d_H1[row*HID + lane];
    float v1 = d_H1[row*HID + lane + 32];
    float sum = v0 + v1;
    #pragma unroll
    for (int o = 16; o > 0; o >>= 1) sum += __shfl_xor_sync(0xffffffffu, sum, o);
    float mu = sum / 64.0f;
    float d0 = v0-mu, d1 = v1-mu;
    float ss = d0*d0 + d1*d1;
    #pragma unroll
    for (int o = 16; o > 0; o >>= 1) ss += __shfl_xor_sync(0xffffffffu, ss, o);
    float rstd = 1.0f / sqrtf(ss/64.0f + 1e-5f);
    float w = n2w[n], b = n2b[n];
    d_H1[row*HID + lane]      = siluf(d0*rstd*w + b);
    d_H1[row*HID + lane + 32] = siluf(d1*rstd*w + b);
}

// ---------------- G = H1' @ W2^T + b2 + trend @ Wt^T + bt ----------------
__global__ void k_G(const float* __restrict__ W2w, const float* __restrict__ W2b,
                    const float* __restrict__ Wtw, const float* __restrict__ Wtb) {
    int id = blockIdx.x * blockDim.x + threadIdx.x;
    if (id >= BN*HID) return;
    int row = id >> 6, h = id & 63;
    float a = W2b[h] + Wtb[h];
    const float* h1 = d_H1 + row*HID;
    const float* w2 = W2w + h*HID;
    #pragma unroll 8
    for (int k = 0; k < HID; ++k) a += h1[k] * w2[k];
    const float* tr = d_trend + (size_t)row*TT;
    const float* wt = Wtw + h*TT;
    #pragma unroll 8
    for (int t = 0; t < TT; ++t) a += tr[t] * wt[t];
    d_G[id] = a;
}

// ---------------- out = G @ W3^T + b3 ----------------
__global__ void k_out(const float* __restrict__ W3w, const float* __restrict__ W3b,
                      float* __restrict__ out) {
    int id = blockIdx.x * blockDim.x + threadIdx.x;
    if (id >= BN*PRED) return;
    int row = id / PRED, t = id % PRED;
    float a = W3b[t];
    const float* g = d_G + row*HID;
    const float* w = W3w + t*HID;
    #pragma unroll 8
    for (int h = 0; h < HID; ++h) a += g[h] * w[h];
    out[id] = a;
}

// ---------------- launch ----------------
extern "C" void kernel_launch(void* const* d_in, const int* in_sizes, int n_in,
                              void* d_out, int out_size) {
    const float* x     = (const float*)d_in[0];
    const float* approx= (const float*)d_in[1];
    const float* theta = (const float*)d_in[2];
    const float* frWr  = (const float*)d_in[3];
    const float* frWi  = (const float*)d_in[4];
    const float* eoWr  = (const float*)d_in[5];
    const float* eoWi  = (const float*)d_in[6];
    const float* femb  = (const float*)d_in[7];
    const float* n1w   = (const float*)d_in[8];
    const float* n1b   = (const float*)d_in[9];
    const float* n2w   = (const float*)d_in[10];
    const float* n2b   = (const float*)d_in[11];
    const float* W1w   = (const float*)d_in[12];
    const float* W1b   = (const float*)d_in[13];
    const float* W2w   = (const float*)d_in[14];
    const float* W2b   = (const float*)d_in[15];
    const float* Wtw   = (const float*)d_in[16];
    const float* Wtb   = (const float*)d_in[17];
    const float* W3w   = (const float*)d_in[18];
    const float* W3b   = (const float*)d_in[19];
    float* out = (float*)d_out;

    k_zero<<<(BM*CC + 255)/256, 256>>>();
    k_pre<<<CC+1, 128>>>(femb, frWr, frWi);
    k_trend_dft<<<(BN+255)/256, 256>>>(x);
    {
        dim3 grid(MM/256, BB, NSL);
        k_knn_part<<<grid, 256>>>();
    }
    k_knn_merge<<<(BM+255)/256, 256>>>();
    k_dinv<<<(BM+255)/256, 256>>>();
    k_g<<<(BM*KNN + 255)/256, 256>>>();
    k_g2<<<(BM*KNN + 255)/256, 256>>>();
    k_proj<<<(BM*32 + 255)/256, 256>>>(approx, theta, eoWr, eoWi);
    k_irfft<<<(BN*32 + 255)/256, 256>>>(n1w, n1b);
    k_H1<<<(BN*HID + 255)/256, 256>>>(W1w, W1b);
    k_inorm2<<<(BN*32 + 255)/256, 256>>>(n2w, n2b);
    k_G<<<(BN*HID + 255)/256, 256>>>(W2w, W2b, Wtw, Wtb);
    k_out<<<(BN*PRED + 255)/256, 256>>>(W3w, W3b, out);
}